// round 12
// baseline (speedup 1.0000x reference)
#include <cuda_runtime.h>

// Problem shape (fixed by reference setup_inputs): [B=64, S=2048, D=512] fp32
constexpr int B = 64;
constexpr int S = 2048;
constexpr int D = 512;
constexpr int D4 = D / 4;                      // 128 float4 per row
constexpr int CHUNK = 16;                      // timesteps per warp
constexpr int THREADS = 256;                   // 8 warps/block (measured best shape)
constexpr int WARPS_PER_BLOCK = THREADS / 32;  // 8
constexpr int ROWS_PER_BLOCK = WARPS_PER_BLOCK * CHUNK;       // 128
constexpr int BLOCKS_PER_BATCH = S / ROWS_PER_BLOCK;          // 16
constexpr int GRID1 = B * BLOCKS_PER_BATCH;                   // 1024 blocks

__device__ __forceinline__ float4 ldcs4(const float4* p) {
    return __ldcs(p);   // streaming: read-once data, don't fight for L2 residency
}

// Kernel 1: squared L2 of consecutive-row diffs (R8 body, max-tracking removed).
// __launch_bounds__(256,7): cap regs at 36 so all 1024 blocks are resident in a
// SINGLE wave (7 CTAs/SM x 148 = 1036), eliminating the wave-2 straggler tail.
// Plain stores only; no atomics, no cross-block sync (locked rules).
__global__ void __launch_bounds__(THREADS, 7)
l2_diff_kernel(const float4* __restrict__ x, float* __restrict__ out) {
    __shared__ float4 s_bound[WARPS_PER_BLOCK * 128];  // 8 rows x 512 floats = 16KB

    const int b    = blockIdx.x / BLOCKS_PER_BATCH;
    const int r0   = (blockIdx.x % BLOCKS_PER_BATCH) * ROWS_PER_BLOCK;
    const int w    = threadIdx.x >> 5;
    const int lane = threadIdx.x & 31;
    const int s0   = r0 + w * CHUNK;

    const float4* base = x + (size_t)b * S * D4;
    float* orow = out + (size_t)b * S;

    // Phase 1: load my chunk's LAST row; share it with warp w+1 via smem.
    float4 last[4];
    {
        const float4* rl = base + (size_t)(s0 + CHUNK - 1) * D4 + lane;
        #pragma unroll
        for (int j = 0; j < 4; ++j) last[j] = ldcs4(rl + 32 * j);
        float4* sm = s_bound + w * 128 + lane;
        #pragma unroll
        for (int j = 0; j < 4; ++j) sm[32 * j] = last[j];
    }

    // Warp 0 also loads the block's global boundary row.
    float4 prev[4];
    const bool first_chunk = (r0 == 0) && (w == 0);
    if (w == 0) {
        const int sprev = (r0 == 0) ? 0 : (r0 - 1);
        const float4* rp = base + (size_t)sprev * D4 + lane;
        #pragma unroll
        for (int j = 0; j < 4; ++j) prev[j] = ldcs4(rp + 32 * j);
    }

    __syncthreads();

    if (w != 0) {
        const float4* sp = s_bound + (w - 1) * 128 + lane;
        #pragma unroll
        for (int j = 0; j < 4; ++j) prev[j] = sp[32 * j];
    }

    if (first_chunk && lane == 0) orow[0] = 0.0f;

    const int s_start = first_chunk ? 1 : s0;
    const int s_last  = s0 + CHUNK - 1;

    for (int s = s_start; s <= s_last; ++s) {
        float4 cur[4];
        if (s < s_last) {
            const float4* row = base + (size_t)s * D4 + lane;
            #pragma unroll
            for (int j = 0; j < 4; ++j) cur[j] = ldcs4(row + 32 * j);
        } else {
            #pragma unroll
            for (int j = 0; j < 4; ++j) cur[j] = last[j];
        }

        float sum = 0.0f;
        #pragma unroll
        for (int j = 0; j < 4; ++j) {
            float dx = cur[j].x - prev[j].x;
            float dy = cur[j].y - prev[j].y;
            float dz = cur[j].z - prev[j].z;
            float dw = cur[j].w - prev[j].w;
            sum += dx * dx + dy * dy + dz * dz + dw * dw;
        }
        // warp reduce (sum over D)
        #pragma unroll
        for (int off = 16; off > 0; off >>= 1)
            sum += __shfl_xor_sync(0xffffffffu, sum, off);
        if (lane == 0) orow[s] = sum;

        #pragma unroll
        for (int j = 0; j < 4; ++j) prev[j] = cur[j];
    }

#if __CUDA_ARCH__ >= 900
    cudaTriggerProgrammaticLaunchCompletion();
#endif
}

// Kernel 2: R5-style fused max+scale (best measured normalize: 4.58us), one block
// per batch, single pass over registers, + PDL grid-dependency sync.
constexpr int NTHREADS2 = 512;                 // = S/4 float4 per row
constexpr int NWARPS2 = NTHREADS2 / 32;        // 16

__global__ void __launch_bounds__(NTHREADS2)
normalize_kernel(float4* __restrict__ out) {
    const int b = blockIdx.x;
    float4* row = out + (size_t)b * (S / 4);

#if __CUDA_ARCH__ >= 900
    cudaGridDependencySynchronize();   // kernel 1's writes become visible
#endif

    float4 v = row[threadIdx.x];
    float m = fmaxf(fmaxf(v.x, v.y), fmaxf(v.z, v.w));

    #pragma unroll
    for (int off = 16; off > 0; off >>= 1)
        m = fmaxf(m, __shfl_xor_sync(0xffffffffu, m, off));

    __shared__ float s_wmax[NWARPS2];
    __shared__ float s_inv;
    const int wid = threadIdx.x >> 5;
    const int lid = threadIdx.x & 31;
    if (lid == 0) s_wmax[wid] = m;
    __syncthreads();

    if (threadIdx.x < 32) {
        float t = (threadIdx.x < NWARPS2) ? s_wmax[threadIdx.x] : 0.0f;
        #pragma unroll
        for (int off = 8; off > 0; off >>= 1)
            t = fmaxf(t, __shfl_xor_sync(0xffffffffu, t, off));
        if (threadIdx.x == 0) s_inv = 1.0f / t;
    }
    __syncthreads();

    const float inv = s_inv;
    v.x *= inv; v.y *= inv; v.z *= inv; v.w *= inv;
    row[threadIdx.x] = v;
}

extern "C" void kernel_launch(void* const* d_in, const int* in_sizes, int n_in,
                              void* d_out, int out_size) {
    const float4* x = (const float4*)d_in[0];
    (void)in_sizes; (void)n_in; (void)out_size;

    l2_diff_kernel<<<GRID1, THREADS>>>(x, (float*)d_out);

    // PDL: normalize's blocks may be scheduled while kernel 1 drains; the
    // cudaGridDependencySynchronize() inside gates the data reads.
    cudaLaunchConfig_t cfg = {};
    cfg.gridDim  = dim3(B);
    cfg.blockDim = dim3(NTHREADS2);
    cudaLaunchAttribute attrs[1];
    attrs[0].id = cudaLaunchAttributeProgrammaticStreamSerialization;
    attrs[0].val.programmaticStreamSerializationAllowed = 1;
    cfg.attrs = attrs;
    cfg.numAttrs = 1;
    float4* o4 = (float4*)d_out;
    cudaLaunchKernelEx(&cfg, normalize_kernel, o4);
}

// round 13
// speedup vs baseline: 1.2287x; 1.2287x over previous
#include <cuda_runtime.h>

// Problem shape (fixed by reference setup_inputs): [B=64, S=2048, D=512] fp32
constexpr int B = 64;
constexpr int S = 2048;
constexpr int D = 512;
constexpr int D4 = D / 4;                      // 128 float4 per row
constexpr int CHUNK = 16;                      // timesteps per warp
constexpr int THREADS = 256;                   // 8 warps/block (measured best shape)
constexpr int WARPS_PER_BLOCK = THREADS / 32;  // 8
constexpr int ROWS_PER_BLOCK = WARPS_PER_BLOCK * CHUNK;       // 128
constexpr int BLOCKS_PER_BATCH = S / ROWS_PER_BLOCK;          // 16
constexpr int GRID1 = B * BLOCKS_PER_BATCH;                   // 1024 blocks

// Per-block max scratch. Plain stores only — NO atomics, NO in-kernel cross-block
// sync (R3/R4/R9/R10: any coordination tail in the streaming kernel costs 10-25us).
__device__ float g_blockmax[GRID1];

__device__ __forceinline__ float4 ldcs4(const float4* p) {
    return __ldcs(p);   // streaming: read-once data, don't fight for L2 residency
}

// Kernel 1 (R8/R11 body — measured best at 44.6us; natural regs ~40, 6 CTAs/SM.
// R12 lesson: do NOT force occupancy — spills cost more than the wave tail).
// Delta vs R11: output stores deferred and coalesced — lane (s-s0) banks the
// row's sum; one 64B store per warp at the end instead of 16 scalar stores.
__global__ void __launch_bounds__(THREADS)
l2_diff_kernel(const float4* __restrict__ x, float* __restrict__ out) {
    __shared__ float4 s_bound[WARPS_PER_BLOCK * 128];  // 8 rows x 512 floats = 16KB
    __shared__ float  s_wmax[WARPS_PER_BLOCK];

    const int b    = blockIdx.x / BLOCKS_PER_BATCH;
    const int r0   = (blockIdx.x % BLOCKS_PER_BATCH) * ROWS_PER_BLOCK;
    const int w    = threadIdx.x >> 5;
    const int lane = threadIdx.x & 31;
    const int s0   = r0 + w * CHUNK;

    const float4* base = x + (size_t)b * S * D4;
    float* orow = out + (size_t)b * S;

    // Phase 1: load my chunk's LAST row; share it with warp w+1 via smem.
    float4 last[4];
    {
        const float4* rl = base + (size_t)(s0 + CHUNK - 1) * D4 + lane;
        #pragma unroll
        for (int j = 0; j < 4; ++j) last[j] = ldcs4(rl + 32 * j);
        float4* sm = s_bound + w * 128 + lane;
        #pragma unroll
        for (int j = 0; j < 4; ++j) sm[32 * j] = last[j];
    }

    // Warp 0 also loads the block's global boundary row.
    float4 prev[4];
    const bool first_chunk = (r0 == 0) && (w == 0);
    if (w == 0) {
        const int sprev = (r0 == 0) ? 0 : (r0 - 1);
        const float4* rp = base + (size_t)sprev * D4 + lane;
        #pragma unroll
        for (int j = 0; j < 4; ++j) prev[j] = ldcs4(rp + 32 * j);
    }

    __syncthreads();

    if (w != 0) {
        const float4* sp = s_bound + (w - 1) * 128 + lane;
        #pragma unroll
        for (int j = 0; j < 4; ++j) prev[j] = sp[32 * j];
    }

    const int s_start = first_chunk ? 1 : s0;   // first chunk: d[0] = 0 (banked below)
    const int s_last  = s0 + CHUNK - 1;

    float wmax  = 0.0f;  // d >= 0 everywhere (and d[0] = 0)
    float mysum = 0.0f;  // lane (s - s0) banks row s's sum; lane 0 of the first
                         // chunk never matches (s starts at s0+1) -> keeps 0 = d[0]

    for (int s = s_start; s <= s_last; ++s) {
        float4 cur[4];
        if (s < s_last) {
            const float4* row = base + (size_t)s * D4 + lane;
            #pragma unroll
            for (int j = 0; j < 4; ++j) cur[j] = ldcs4(row + 32 * j);
        } else {
            #pragma unroll
            for (int j = 0; j < 4; ++j) cur[j] = last[j];
        }

        float sum = 0.0f;
        #pragma unroll
        for (int j = 0; j < 4; ++j) {
            float dx = cur[j].x - prev[j].x;
            float dy = cur[j].y - prev[j].y;
            float dz = cur[j].z - prev[j].z;
            float dw = cur[j].w - prev[j].w;
            sum += dx * dx + dy * dy + dz * dz + dw * dw;
        }
        // warp reduce (sum over D); all lanes end with the full sum
        #pragma unroll
        for (int off = 16; off > 0; off >>= 1)
            sum += __shfl_xor_sync(0xffffffffu, sum, off);
        wmax = fmaxf(wmax, sum);
        if (s - s0 == lane) mysum = sum;        // bank instead of store

        #pragma unroll
        for (int j = 0; j < 4; ++j) prev[j] = cur[j];
    }

    // One coalesced 64B store per warp (lanes 0..15 -> rows s0..s0+15).
    if (lane < CHUNK) orow[s0 + lane] = mysum;

    // Block max -> plain store (NOT atomic), then PDL trigger.
    if (lane == 0) s_wmax[w] = wmax;
    __syncthreads();
    if (threadIdx.x == 0) {
        float m = s_wmax[0];
        #pragma unroll
        for (int i = 1; i < WARPS_PER_BLOCK; ++i) m = fmaxf(m, s_wmax[i]);
        g_blockmax[blockIdx.x] = m;
    }
#if __CUDA_ARCH__ >= 900
    cudaTriggerProgrammaticLaunchCompletion();
#endif
}

// Kernel 2: near-elementwise normalize (R8/R11 version) + PDL dependency sync.
constexpr int NTHREADS2 = 256;
constexpr int F2_PER_BATCH = S / 2;                     // 1024
constexpr int GRID2 = (B * S / 2) / NTHREADS2;          // 256 blocks

__global__ void __launch_bounds__(NTHREADS2)
normalize_kernel(float2* __restrict__ out) {
    const int i = blockIdx.x * NTHREADS2 + threadIdx.x;  // float2 index
    const int b = blockIdx.x / (F2_PER_BATCH / NTHREADS2);  // 4 blocks per batch
    const int lane = threadIdx.x & 31;
    const int eidx = b * BLOCKS_PER_BATCH + (lane & 15);

#if __CUDA_ARCH__ >= 900
    cudaGridDependencySynchronize();   // kernel 1's writes become visible
#endif

    float m = g_blockmax[eidx];
    #pragma unroll
    for (int off = 8; off > 0; off >>= 1)
        m = fmaxf(m, __shfl_xor_sync(0xffffffffu, m, off));
    const float inv = 1.0f / m;

    float2 v = out[i];
    v.x *= inv; v.y *= inv;
    out[i] = v;
}

extern "C" void kernel_launch(void* const* d_in, const int* in_sizes, int n_in,
                              void* d_out, int out_size) {
    const float4* x = (const float4*)d_in[0];
    (void)in_sizes; (void)n_in; (void)out_size;

    l2_diff_kernel<<<GRID1, THREADS>>>(x, (float*)d_out);

    // PDL: normalize's blocks may be scheduled while kernel 1 drains; the
    // cudaGridDependencySynchronize() inside gates the data reads.
    cudaLaunchConfig_t cfg = {};
    cfg.gridDim  = dim3(GRID2);
    cfg.blockDim = dim3(NTHREADS2);
    cudaLaunchAttribute attrs[1];
    attrs[0].id = cudaLaunchAttributeProgrammaticStreamSerialization;
    attrs[0].val.programmaticStreamSerializationAllowed = 1;
    cfg.attrs = attrs;
    cfg.numAttrs = 1;
    float2* o2 = (float2*)d_out;
    cudaLaunchKernelEx(&cfg, normalize_kernel, o2);
}